// round 9
// baseline (speedup 1.0000x reference)
#include <cuda_runtime.h>
#include <math.h>
#include <stdint.h>

// Problem constants
#define NN      1024
#define DF      6
#define TT      60
#define HH      64
#define GG      192      // 3*H
#define RR      64
#define WPAD    68
#define HPAD    68
#define NEG_VAL (-10000.0f)
#define SLOPE   0.01f

// Inter-kernel scratch
__device__ float g_h1[NN * HH];
__device__ float g_sa[NN];
__device__ float g_sb[NN];
__device__ float g_dot[NN * NN];
__device__ float g_sum[NN * NN];

typedef unsigned long long u64;

__device__ __forceinline__ u64 ffma2(u64 a, u64 b, u64 c) {
    u64 d;
    asm("fma.rn.f32x2 %0, %1, %2, %3;" : "=l"(d) : "l"(a), "l"(b), "l"(c));
    return d;
}
__device__ __forceinline__ float hsum2(u64 v) {
    float lo, hi;
    asm("mov.b64 {%0,%1}, %2;" : "=f"(lo), "=f"(hi) : "l"(v));
    return lo + hi;
}
__device__ __forceinline__ float tanh_fast(float x) {
    float y;
    asm("tanh.approx.f32 %0, %1;" : "=f"(y) : "f"(x));
    return y;
}
__device__ __forceinline__ float sig_fast(float x) {
    return 0.5f * tanh_fast(0.5f * x) + 0.5f;
}

// Compacting 4-lane reduction over kq (lane bits 0-1). After this, the caller
// lane owns row rfin = (kq&1)*2 + (kq>>1) with the fully-reduced value.
#define REDUCE4(v0, v1, v2, v3, out)                                          \
    {                                                                         \
        float _t0 = __shfl_xor_sync(0xffffffffu, hiA ? (v0) : (v2), 1);       \
        float _t1 = __shfl_xor_sync(0xffffffffu, hiA ? (v1) : (v3), 1);       \
        float _va = (hiA ? (v2) : (v0)) + _t0;                                \
        float _vb = (hiA ? (v3) : (v1)) + _t1;                                \
        float _t2 = __shfl_xor_sync(0xffffffffu, hiB ? _va : _vb, 2);         \
        (out) = (hiB ? _vb : _va) + _t2;                                      \
    }

// ---------------------------------------------------------------------------
// Kernel 1: fused 2-layer GRU v4: 512 threads (16 warps) per block,
// one column per thread, r=4 row-group, s=4 stride-K split.
// ---------------------------------------------------------------------------
#define GT 512
#define GRU_ROWS 8

__global__ void __launch_bounds__(GT, 1)
gru_kernel(const float* __restrict__ x,
           const float* __restrict__ Wih0, const float* __restrict__ Whh0,
           const float* __restrict__ bih0, const float* __restrict__ bhh0,
           const float* __restrict__ Wih1, const float* __restrict__ Whh1,
           const float* __restrict__ bih1, const float* __restrict__ bhh1,
           const float* __restrict__ Wv)
{
    extern __shared__ float smem[];
    float* sWhh0 = smem;                          // 192*68
    float* sWih1 = sWhh0 + GG * WPAD;             // 192*68
    float* sWhh1 = sWih1 + GG * WPAD;             // 192*68
    float* sWih0 = sWhh1 + GG * WPAD;             // 192*8
    float* sX    = sWih0 + GG * 8;                // 8*360
    float* sXt   = sX + GRU_ROWS * 360;           // 2*64
    float* sH0   = sXt + 2 * 64;                  // 2*8*68 (double buffer)
    float* sH1   = sH0 + 2 * GRU_ROWS * HPAD;     // 2*8*68

    const int tid = threadIdx.x;
    const int r0  = blockIdx.x * GRU_ROWS;

    for (int i = tid; i < GG * HH; i += GT) {
        int o = i >> 6, k = i & 63;
        sWhh0[o * WPAD + k] = Whh0[i];
        sWih1[o * WPAD + k] = Wih1[i];
        sWhh1[o * WPAD + k] = Whh1[i];
    }
    for (int i = tid; i < GG * DF; i += GT) {
        int o = i / DF, d = i % DF;
        sWih0[o * 8 + d] = Wih0[i];
    }
    for (int i = tid; i < GRU_ROWS * 360; i += GT) {
        int r = i / 360, cc = i % 360;
        sX[i] = x[(size_t)(r0 + r) * 360 + cc];
    }
    for (int i = tid; i < 2 * GRU_ROWS * HPAD; i += GT) {
        sH0[i] = 0.f; sH1[i] = 0.f;
    }
    if (tid < GRU_ROWS * DF) {
        int r = tid / DF, d = tid % DF;
        sXt[r * 8 + d] = sX[r * 360 + d * TT + 0];
    }

    // thread mapping: 16 warps; each lane -> (kq, rg, cpl); c = warp*4+cpl
    const int lane  = tid & 31;
    const int warp  = tid >> 5;
    const int kq    = lane & 3;
    const int rg    = (lane >> 2) & 1;
    const int cpl   = lane >> 3;
    const int c     = warp * 4 + cpl;       // 0..63
    const int rbase = rg * 4;
    const bool hiA  = (kq & 1);
    const bool hiB  = ((kq >> 1) & 1);
    const int rfin  = (kq & 1) * 2 + (kq >> 1);
    const int myrow = rbase + rfin;

    // per-lane biases for column c
    const float br0  = bih0[c] + bhh0[c];
    const float bz0  = bih0[64 + c] + bhh0[64 + c];
    const float bxn0 = bih0[128 + c];
    const float bhn0 = bhh0[128 + c];
    const float br1  = bih1[c] + bhh1[c];
    const float bz1  = bih1[64 + c] + bhh1[64 + c];
    const float bxn1 = bih1[128 + c];
    const float bhn1 = bhh1[128 + c];
    __syncthreads();

    for (int t = 0; t < TT; ++t) {
        const int cur = t & 1, nxt = cur ^ 1;
        float* sH0c = sH0 + cur * (GRU_ROWS * HPAD);
        float* sH0n = sH0 + nxt * (GRU_ROWS * HPAD);
        float* sH1c = sH1 + cur * (GRU_ROWS * HPAD);
        float* sH1n = sH1 + nxt * (GRU_ROWS * HPAD);

        // ================= layer 0: gemm + reduce + gates =================
        {
            u64 Ar[4], Az[4], An[4];
            #pragma unroll
            for (int i = 0; i < 4; i++) { Ar[i] = 0; Az[i] = 0; An[i] = 0; }

            #pragma unroll
            for (int q = 0; q < 4; q++) {
                const int k4 = q * 4 + kq;
                ulonglong2 wr = *(const ulonglong2*)&sWhh0[c * WPAD + k4 * 4];
                ulonglong2 wz = *(const ulonglong2*)&sWhh0[(64 + c) * WPAD + k4 * 4];
                ulonglong2 wn = *(const ulonglong2*)&sWhh0[(128 + c) * WPAD + k4 * 4];
                #pragma unroll
                for (int i = 0; i < 4; i++) {
                    ulonglong2 hv = *(const ulonglong2*)&sH0c[(rbase + i) * HPAD + k4 * 4];
                    Ar[i] = ffma2(hv.x, wr.x, Ar[i]);
                    Az[i] = ffma2(hv.x, wz.x, Az[i]);
                    An[i] = ffma2(hv.x, wn.x, An[i]);
                    Ar[i] = ffma2(hv.y, wr.y, Ar[i]);
                    Az[i] = ffma2(hv.y, wz.y, Az[i]);
                    An[i] = ffma2(hv.y, wn.y, An[i]);
                }
            }

            float hr, hz, hn;
            {
                float v0, v1, v2, v3;
                v0 = hsum2(Ar[0]); v1 = hsum2(Ar[1]);
                v2 = hsum2(Ar[2]); v3 = hsum2(Ar[3]);
                REDUCE4(v0, v1, v2, v3, hr);
                v0 = hsum2(Az[0]); v1 = hsum2(Az[1]);
                v2 = hsum2(Az[2]); v3 = hsum2(Az[3]);
                REDUCE4(v0, v1, v2, v3, hz);
                v0 = hsum2(An[0]); v1 = hsum2(An[1]);
                v2 = hsum2(An[2]); v3 = hsum2(An[3]);
                REDUCE4(v0, v1, v2, v3, hn);
            }

            // x-side + gates, owner lane: row = myrow, col c
            {
                float xr = 0.f, xz = 0.f, xn = 0.f;
                #pragma unroll
                for (int d = 0; d < DF; d++) {
                    float xv = sXt[cur * 64 + myrow * 8 + d];
                    xr += xv * sWih0[c * 8 + d];
                    xz += xv * sWih0[(64 + c) * 8 + d];
                    xn += xv * sWih0[(128 + c) * 8 + d];
                }
                float rv = sig_fast(xr + hr + br0);
                float zv = sig_fast(xz + hz + bz0);
                float nv = tanh_fast(xn + bxn0 + rv * (hn + bhn0));
                float ho = sH0c[myrow * HPAD + c];
                sH0n[myrow * HPAD + c] = (1.f - zv) * nv + zv * ho;
            }
        }
        if (t + 1 < TT && tid < GRU_ROWS * DF) {
            int r = tid / DF, d = tid % DF;
            sXt[nxt * 64 + r * 8 + d] = sX[r * 360 + d * TT + (t + 1)];
        }
        __syncthreads();

        // ================= layer 1: gemm + reduce + gates =================
        {
            u64 Cr[4], Cz[4], Cxn[4], Chn[4];
            #pragma unroll
            for (int i = 0; i < 4; i++) { Cr[i] = 0; Cz[i] = 0; Cxn[i] = 0; Chn[i] = 0; }

            #pragma unroll
            for (int q = 0; q < 4; q++) {
                const int k4 = q * 4 + kq;
                ulonglong2 ur = *(const ulonglong2*)&sWih1[c * WPAD + k4 * 4];
                ulonglong2 uz = *(const ulonglong2*)&sWih1[(64 + c) * WPAD + k4 * 4];
                ulonglong2 un = *(const ulonglong2*)&sWih1[(128 + c) * WPAD + k4 * 4];
                ulonglong2 wr = *(const ulonglong2*)&sWhh1[c * WPAD + k4 * 4];
                ulonglong2 wz = *(const ulonglong2*)&sWhh1[(64 + c) * WPAD + k4 * 4];
                ulonglong2 wn = *(const ulonglong2*)&sWhh1[(128 + c) * WPAD + k4 * 4];
                #pragma unroll
                for (int i = 0; i < 4; i++) {
                    ulonglong2 gv = *(const ulonglong2*)&sH0n[(rbase + i) * HPAD + k4 * 4];
                    ulonglong2 vv = *(const ulonglong2*)&sH1c[(rbase + i) * HPAD + k4 * 4];
                    Cr[i]  = ffma2(gv.x, ur.x, Cr[i]);
                    Cr[i]  = ffma2(vv.x, wr.x, Cr[i]);
                    Cz[i]  = ffma2(gv.x, uz.x, Cz[i]);
                    Cz[i]  = ffma2(vv.x, wz.x, Cz[i]);
                    Cxn[i] = ffma2(gv.x, un.x, Cxn[i]);
                    Chn[i] = ffma2(vv.x, wn.x, Chn[i]);
                    Cr[i]  = ffma2(gv.y, ur.y, Cr[i]);
                    Cr[i]  = ffma2(vv.y, wr.y, Cr[i]);
                    Cz[i]  = ffma2(gv.y, uz.y, Cz[i]);
                    Cz[i]  = ffma2(vv.y, wz.y, Cz[i]);
                    Cxn[i] = ffma2(gv.y, un.y, Cxn[i]);
                    Chn[i] = ffma2(vv.y, wn.y, Chn[i]);
                }
            }

            {
                float sr, sz, xn, hn;
                float v0, v1, v2, v3;
                v0 = hsum2(Cr[0]); v1 = hsum2(Cr[1]);
                v2 = hsum2(Cr[2]); v3 = hsum2(Cr[3]);
                REDUCE4(v0, v1, v2, v3, sr);
                v0 = hsum2(Cz[0]); v1 = hsum2(Cz[1]);
                v2 = hsum2(Cz[2]); v3 = hsum2(Cz[3]);
                REDUCE4(v0, v1, v2, v3, sz);
                v0 = hsum2(Cxn[0]); v1 = hsum2(Cxn[1]);
                v2 = hsum2(Cxn[2]); v3 = hsum2(Cxn[3]);
                REDUCE4(v0, v1, v2, v3, xn);
                v0 = hsum2(Chn[0]); v1 = hsum2(Chn[1]);
                v2 = hsum2(Chn[2]); v3 = hsum2(Chn[3]);
                REDUCE4(v0, v1, v2, v3, hn);

                float rv = sig_fast(sr + br1);
                float zv = sig_fast(sz + bz1);
                float nv = tanh_fast(xn + bxn1 + rv * (hn + bhn1));
                float ho = sH1c[myrow * HPAD + c];
                sH1n[myrow * HPAD + c] = (1.f - zv) * nv + zv * ho;
            }
        }
        __syncthreads();
    }

    // final h1 buffer = TT & 1
    const float* hf = sH1 + (TT & 1) * (GRU_ROWS * HPAD);
    for (int i = tid; i < GRU_ROWS * HH; i += GT) {
        int r = i >> 6, cc = i & 63;
        g_h1[(size_t)r0 * HH + i] = hf[r * HPAD + cc];
    }
    if (tid < GRU_ROWS) {
        float a = 0.f, b2s = 0.f;
        #pragma unroll
        for (int cc2 = 0; cc2 < HH; cc2++) {
            float h = hf[tid * HPAD + cc2];
            a   += h * Wv[cc2];
            b2s += h * Wv[HH + cc2];
        }
        g_sa[r0 + tid] = a;
        g_sb[r0 + tid] = b2s;
    }
}

// ---------------------------------------------------------------------------
// Kernel 2: streaming rel-dot (unchanged; overlapped with GRU).
// ---------------------------------------------------------------------------
#define RD_THREADS 256
#define RD_BLOCKS  2048

__global__ void __launch_bounds__(RD_THREADS)
reldot_kernel(const float* __restrict__ rel, const float* __restrict__ W)
{
    __shared__ float sWv[RR];
    const int tid = threadIdx.x;
    if (tid < RR) sWv[tid] = W[2 * HH + tid];
    __syncthreads();

    const int lane16 = tid & 15;
    const int grp    = tid >> 4;
    const float4 wv  = *(const float4*)&sWv[lane16 * 4];
    const int stride = RD_BLOCKS * 16;

    for (int p = blockIdx.x * 16 + grp; p < NN * NN; p += stride) {
        float4 v = *(const float4*)&rel[(size_t)p * RR + lane16 * 4];
        float dot  = v.x * wv.x + v.y * wv.y + v.z * wv.z + v.w * wv.w;
        float ssum = v.x + v.y + v.z + v.w;
        #pragma unroll
        for (int off = 8; off; off >>= 1) {
            dot  += __shfl_xor_sync(0xffffffffu, dot,  off);
            ssum += __shfl_xor_sync(0xffffffffu, ssum, off);
        }
        if (lane16 == 0) {
            g_dot[p] = dot;
            g_sum[p] = ssum;
        }
    }
}

// ---------------------------------------------------------------------------
// Kernel 3: softmax + agg + FC, 8 rows per block (unchanged).
// ---------------------------------------------------------------------------
#define A3_THREADS 512

__global__ void __launch_bounds__(A3_THREADS)
att3_kernel(const float* __restrict__ bsc,
            const float* __restrict__ fc_w,
            const float* __restrict__ fc_b,
            float* __restrict__ out)
{
    __shared__ float sP[8 * NN];
    __shared__ float sT[64 * 64];
    __shared__ float sWmax[16];
    __shared__ float sWsum[16];
    __shared__ float sDen[8];
    __shared__ float sRed[16];

    const int tid  = threadIdx.x;
    const int wid  = tid >> 5;
    const int lane = tid & 31;
    const int i0   = blockIdx.x * 8;

    const int r    = wid >> 1;
    const int part = ((wid & 1) << 5) + lane;
    const int i    = i0 + r;
    const float sa_i = g_sa[i];
    const float bval = bsc[0];

    float tv[16];
    float mx = -INFINITY;
    #pragma unroll
    for (int q4 = 0; q4 < 4; q4++) {
        int j = part * 16 + q4 * 4;
        float4 d4 = *(const float4*)&g_dot[(size_t)i * NN + j];
        float4 s4 = *(const float4*)&g_sum[(size_t)i * NN + j];
        #pragma unroll
        for (int e = 0; e < 4; e++) {
            float dot  = (&d4.x)[e];
            float ssum = (&s4.x)[e];
            float w = sa_i + g_sb[j + e] + dot + bval;
            w = (w >= 0.f) ? w : SLOPE * w;
            float m  = (ssum != 0.f) ? 1.f : 0.f;
            float t  = m * w;
            if (t == 0.f) t = NEG_VAL;
            tv[q4 * 4 + e] = t;
            sP[r * NN + j + e] = m;
            mx = fmaxf(mx, t);
        }
    }
    #pragma unroll
    for (int off = 16; off; off >>= 1) mx = fmaxf(mx, __shfl_xor_sync(0xffffffffu, mx, off));
    if (lane == 0) sWmax[wid] = mx;
    __syncthreads();
    mx = fmaxf(sWmax[r * 2], sWmax[r * 2 + 1]);

    float lsum = 0.f;
    #pragma unroll
    for (int q = 0; q < 16; q++) {
        int j = part * 16 + q;
        float e = __expf(tv[q] - mx);
        lsum += e;
        sP[r * NN + j] = e * sP[r * NN + j];
    }
    #pragma unroll
    for (int off = 16; off; off >>= 1) lsum += __shfl_xor_sync(0xffffffffu, lsum, off);
    if (lane == 0) sWsum[wid] = lsum;
    __syncthreads();
    if (tid < 8) sDen[tid] = sWsum[tid * 2] + sWsum[tid * 2 + 1];
    __syncthreads();

    const int c  = tid & 63;
    const int rr = tid >> 6;
    float acc = 0.f;
    for (int tile = 0; tile < 16; tile++) {
        #pragma unroll
        for (int k = 0; k < 8; k++) {
            int e = tid + k * A3_THREADS;
            sT[e] = g_h1[(size_t)(tile * 64) * HH + e];
        }
        __syncthreads();
        const float* pr = &sP[rr * NN + tile * 64];
        #pragma unroll 16
        for (int jj = 0; jj < 64; jj++)
            acc += pr[jj] * sT[jj * 64 + c];
        __syncthreads();
    }

    const float inv = 1.0f / sDen[rr];
    float val = g_h1[(size_t)(i0 + rr) * HH + c] * fc_w[c] + acc * inv * fc_w[HH + c];
    #pragma unroll
    for (int off = 16; off; off >>= 1) val += __shfl_xor_sync(0xffffffffu, val, off);
    if (lane == 0) sRed[wid] = val;
    __syncthreads();
    if (tid < 8)
        out[i0 + tid] = sRed[tid * 2] + sRed[tid * 2 + 1] + fc_b[0];
}

// ---------------------------------------------------------------------------
// Launch: gru first on main stream, reldot forked alongside it.
// ---------------------------------------------------------------------------
extern "C" void kernel_launch(void* const* d_in, const int* in_sizes, int n_in,
                              void* d_out, int out_size)
{
    const float* x    = (const float*)d_in[0];
    const float* rel  = (const float*)d_in[1];
    const float* W    = (const float*)d_in[2];
    const float* b    = (const float*)d_in[3];
    const float* fc_w = (const float*)d_in[4];
    const float* fc_b = (const float*)d_in[5];
    const float* Wih0 = (const float*)d_in[6];
    const float* Whh0 = (const float*)d_in[7];
    const float* bih0 = (const float*)d_in[8];
    const float* bhh0 = (const float*)d_in[9];
    const float* Wih1 = (const float*)d_in[10];
    const float* Whh1 = (const float*)d_in[11];
    const float* bih1 = (const float*)d_in[12];
    const float* bhh1 = (const float*)d_in[13];
    float* out = (float*)d_out;

    const size_t gru_smem =
        (3 * GG * WPAD + GG * 8 + GRU_ROWS * 360 + 2 * 64 +
         4 * GRU_ROWS * HPAD) * sizeof(float);
    cudaFuncSetAttribute(gru_kernel, cudaFuncAttributeMaxDynamicSharedMemorySize,
                         (int)gru_smem);

    cudaStream_t s1;
    cudaEvent_t eFork, eJoin;
    cudaStreamCreateWithFlags(&s1, cudaStreamNonBlocking);
    cudaEventCreateWithFlags(&eFork, cudaEventDisableTiming);
    cudaEventCreateWithFlags(&eJoin, cudaEventDisableTiming);

    cudaEventRecord(eFork, 0);
    cudaStreamWaitEvent(s1, eFork, 0);

    gru_kernel<<<NN / GRU_ROWS, GT, gru_smem>>>(
        x, Wih0, Whh0, bih0, bhh0, Wih1, Whh1, bih1, bhh1, W);

    reldot_kernel<<<RD_BLOCKS, RD_THREADS, 0, s1>>>(rel, W);
    cudaEventRecord(eJoin, s1);

    cudaStreamWaitEvent(0, eJoin, 0);

    att3_kernel<<<NN / 8, A3_THREADS>>>(b, fc_w, fc_b, out);
}

// round 10
// speedup vs baseline: 1.7530x; 1.7530x over previous
#include <cuda_runtime.h>
#include <math.h>
#include <stdint.h>

// Problem constants
#define NN      1024
#define DF      6
#define TT      60
#define HH      64
#define GG      192      // 3*H
#define RR      64
#define WPAD    68
#define HPAD    68
#define NEG_VAL (-10000.0f)
#define SLOPE   0.01f

// Inter-kernel scratch
__device__ float g_h1[NN * HH];
__device__ float g_sa[NN];
__device__ float g_sb[NN];
__device__ float g_dot[NN * NN];
__device__ float g_sum[NN * NN];

typedef unsigned long long u64;

__device__ __forceinline__ u64 ffma2(u64 a, u64 b, u64 c) {
    u64 d;
    asm("fma.rn.f32x2 %0, %1, %2, %3;" : "=l"(d) : "l"(a), "l"(b), "l"(c));
    return d;
}
__device__ __forceinline__ float hsum2(u64 v) {
    float lo, hi;
    asm("mov.b64 {%0,%1}, %2;" : "=f"(lo), "=f"(hi) : "l"(v));
    return lo + hi;
}
__device__ __forceinline__ float tanh_fast(float x) {
    float y;
    asm("tanh.approx.f32 %0, %1;" : "=f"(y) : "f"(x));
    return y;
}
__device__ __forceinline__ float sig_fast(float x) {
    return 0.5f * tanh_fast(0.5f * x) + 0.5f;
}

// Compacting 4-lane reduction over kq (lane bits 0-1). After this, the caller
// lane owns row rfin = (kq&1)*2 + (kq>>1) with the fully-reduced value.
#define REDUCE4(v0, v1, v2, v3, out)                                          \
    {                                                                         \
        float _t0 = __shfl_xor_sync(0xffffffffu, hiA ? (v0) : (v2), 1);       \
        float _t1 = __shfl_xor_sync(0xffffffffu, hiA ? (v1) : (v3), 1);       \
        float _va = (hiA ? (v2) : (v0)) + _t0;                                \
        float _vb = (hiA ? (v3) : (v1)) + _t1;                                \
        float _t2 = __shfl_xor_sync(0xffffffffu, hiB ? _va : _vb, 2);         \
        (out) = (hiB ? _vb : _va) + _t2;                                      \
    }

// ---------------------------------------------------------------------------
// Kernel 1: fused 2-layer GRU (R8 version, 256 threads, 2 cols/thread).
// ---------------------------------------------------------------------------
#define GRU_THREADS 256
#define GRU_ROWS    8

__global__ void __launch_bounds__(GRU_THREADS, 1)
gru_kernel(const float* __restrict__ x,
           const float* __restrict__ Wih0, const float* __restrict__ Whh0,
           const float* __restrict__ bih0, const float* __restrict__ bhh0,
           const float* __restrict__ Wih1, const float* __restrict__ Whh1,
           const float* __restrict__ bih1, const float* __restrict__ bhh1,
           const float* __restrict__ Wv)
{
    extern __shared__ float smem[];
    float* sWhh0 = smem;                          // 192*68
    float* sWih1 = sWhh0 + GG * WPAD;             // 192*68
    float* sWhh1 = sWih1 + GG * WPAD;             // 192*68
    float* sWih0 = sWhh1 + GG * WPAD;             // 192*8
    float* sX    = sWih0 + GG * 8;                // 8*360
    float* sXt   = sX + GRU_ROWS * 360;           // 2*64
    float* sH0   = sXt + 2 * 64;                  // 2*8*68 (double buffer)
    float* sH1   = sH0 + 2 * GRU_ROWS * HPAD;     // 2*8*68

    const int tid = threadIdx.x;
    const int r0  = blockIdx.x * GRU_ROWS;

    for (int i = tid; i < GG * HH; i += GRU_THREADS) {
        int o = i >> 6, k = i & 63;
        sWhh0[o * WPAD + k] = Whh0[i];
        sWih1[o * WPAD + k] = Wih1[i];
        sWhh1[o * WPAD + k] = Whh1[i];
    }
    for (int i = tid; i < GG * DF; i += GRU_THREADS) {
        int o = i / DF, d = i % DF;
        sWih0[o * 8 + d] = Wih0[i];
    }
    for (int i = tid; i < GRU_ROWS * 360; i += GRU_THREADS) {
        int r = i / 360, cc = i % 360;
        sX[i] = x[(size_t)(r0 + r) * 360 + cc];
    }
    for (int i = tid; i < 2 * GRU_ROWS * HPAD; i += GRU_THREADS) {
        sH0[i] = 0.f; sH1[i] = 0.f;
    }
    if (tid < GRU_ROWS * DF) {
        int r = tid / DF, d = tid % DF;
        sXt[r * 8 + d] = sX[r * 360 + d * TT + 0];
    }

    // thread mapping
    const int lane  = tid & 31;
    const int warp  = tid >> 5;
    const int kq    = lane & 3;            // K split index (stride-4 chunks)
    const int rg    = (lane >> 2) & 1;     // row group
    const int cpl   = lane >> 3;           // 0..3
    const int cp    = warp * 4 + cpl;      // 0..31
    const int rbase = rg * 4;
    const int c0    = cp;
    const int c1    = cp + 32;
    const bool hiA  = (kq & 1);
    const bool hiB  = ((kq >> 1) & 1);
    const int rfin  = (kq & 1) * 2 + (kq >> 1);
    const int myrow = rbase + rfin;

    // per-lane biases for cols {c0, c1}
    float br0[2], bz0[2], bxn0[2], bhn0[2];
    float br1[2], bz1[2], bxn1[2], bhn1[2];
    {
        const int cc[2] = {c0, c1};
        #pragma unroll
        for (int j = 0; j < 2; j++) {
            br0[j]  = bih0[cc[j]] + bhh0[cc[j]];
            bz0[j]  = bih0[64 + cc[j]] + bhh0[64 + cc[j]];
            bxn0[j] = bih0[128 + cc[j]];
            bhn0[j] = bhh0[128 + cc[j]];
            br1[j]  = bih1[cc[j]] + bhh1[cc[j]];
            bz1[j]  = bih1[64 + cc[j]] + bhh1[64 + cc[j]];
            bxn1[j] = bih1[128 + cc[j]];
            bhn1[j] = bhh1[128 + cc[j]];
        }
    }
    __syncthreads();

    for (int t = 0; t < TT; ++t) {
        const int cur = t & 1, nxt = cur ^ 1;
        float* sH0c = sH0 + cur * (GRU_ROWS * HPAD);
        float* sH0n = sH0 + nxt * (GRU_ROWS * HPAD);
        float* sH1c = sH1 + cur * (GRU_ROWS * HPAD);
        float* sH1n = sH1 + nxt * (GRU_ROWS * HPAD);

        // ================= layer 0: gemm + reduce + gates =================
        {
            u64 Ar[4][2], Az[4][2], An[4][2];
            #pragma unroll
            for (int i = 0; i < 4; i++)
                #pragma unroll
                for (int j = 0; j < 2; j++) { Ar[i][j] = 0; Az[i][j] = 0; An[i][j] = 0; }

            #pragma unroll
            for (int q = 0; q < 4; q++) {
                const int k4 = q * 4 + kq;
                ulonglong2 wr0 = *(const ulonglong2*)&sWhh0[c0 * WPAD + k4 * 4];
                ulonglong2 wr1 = *(const ulonglong2*)&sWhh0[c1 * WPAD + k4 * 4];
                ulonglong2 wz0 = *(const ulonglong2*)&sWhh0[(64 + c0) * WPAD + k4 * 4];
                ulonglong2 wz1 = *(const ulonglong2*)&sWhh0[(64 + c1) * WPAD + k4 * 4];
                ulonglong2 wn0 = *(const ulonglong2*)&sWhh0[(128 + c0) * WPAD + k4 * 4];
                ulonglong2 wn1 = *(const ulonglong2*)&sWhh0[(128 + c1) * WPAD + k4 * 4];
                #pragma unroll
                for (int i = 0; i < 4; i++) {
                    ulonglong2 hv = *(const ulonglong2*)&sH0c[(rbase + i) * HPAD + k4 * 4];
                    Ar[i][0] = ffma2(hv.x, wr0.x, Ar[i][0]);
                    Ar[i][1] = ffma2(hv.x, wr1.x, Ar[i][1]);
                    Az[i][0] = ffma2(hv.x, wz0.x, Az[i][0]);
                    Az[i][1] = ffma2(hv.x, wz1.x, Az[i][1]);
                    An[i][0] = ffma2(hv.x, wn0.x, An[i][0]);
                    An[i][1] = ffma2(hv.x, wn1.x, An[i][1]);
                    Ar[i][0] = ffma2(hv.y, wr0.y, Ar[i][0]);
                    Ar[i][1] = ffma2(hv.y, wr1.y, Ar[i][1]);
                    Az[i][0] = ffma2(hv.y, wz0.y, Az[i][0]);
                    Az[i][1] = ffma2(hv.y, wz1.y, Az[i][1]);
                    An[i][0] = ffma2(hv.y, wn0.y, An[i][0]);
                    An[i][1] = ffma2(hv.y, wn1.y, An[i][1]);
                }
            }

            float hr[2], hz[2], hn[2];
            #pragma unroll
            for (int j = 0; j < 2; j++) {
                float v0, v1, v2, v3;
                v0 = hsum2(Ar[0][j]); v1 = hsum2(Ar[1][j]);
                v2 = hsum2(Ar[2][j]); v3 = hsum2(Ar[3][j]);
                REDUCE4(v0, v1, v2, v3, hr[j]);
                v0 = hsum2(Az[0][j]); v1 = hsum2(Az[1][j]);
                v2 = hsum2(Az[2][j]); v3 = hsum2(Az[3][j]);
                REDUCE4(v0, v1, v2, v3, hz[j]);
                v0 = hsum2(An[0][j]); v1 = hsum2(An[1][j]);
                v2 = hsum2(An[2][j]); v3 = hsum2(An[3][j]);
                REDUCE4(v0, v1, v2, v3, hn[j]);
            }

            // x-side + gates, owner lane: row = myrow, cols c0/c1
            const int cc[2] = {c0, c1};
            #pragma unroll
            for (int j = 0; j < 2; j++) {
                float xr = 0.f, xz = 0.f, xn = 0.f;
                #pragma unroll
                for (int d = 0; d < DF; d++) {
                    float xv = sXt[cur * 64 + myrow * 8 + d];
                    xr += xv * sWih0[cc[j] * 8 + d];
                    xz += xv * sWih0[(64 + cc[j]) * 8 + d];
                    xn += xv * sWih0[(128 + cc[j]) * 8 + d];
                }
                float rv = sig_fast(xr + hr[j] + br0[j]);
                float zv = sig_fast(xz + hz[j] + bz0[j]);
                float nv = tanh_fast(xn + bxn0[j] + rv * (hn[j] + bhn0[j]));
                float ho = sH0c[myrow * HPAD + cc[j]];
                sH0n[myrow * HPAD + cc[j]] = (1.f - zv) * nv + zv * ho;
            }
        }
        if (t + 1 < TT && tid < GRU_ROWS * DF) {
            int r = tid / DF, d = tid % DF;
            sXt[nxt * 64 + r * 8 + d] = sX[r * 360 + d * TT + (t + 1)];
        }
        __syncthreads();

        // ================= layer 1: gemm + reduce + gates =================
        {
            u64 Cr[4][2], Cz[4][2], Cxn[4][2], Chn[4][2];
            #pragma unroll
            for (int i = 0; i < 4; i++)
                #pragma unroll
                for (int j = 0; j < 2; j++) { Cr[i][j] = 0; Cz[i][j] = 0; Cxn[i][j] = 0; Chn[i][j] = 0; }

            #pragma unroll
            for (int q = 0; q < 4; q++) {
                const int k4 = q * 4 + kq;
                ulonglong2 ur0 = *(const ulonglong2*)&sWih1[c0 * WPAD + k4 * 4];
                ulonglong2 ur1 = *(const ulonglong2*)&sWih1[c1 * WPAD + k4 * 4];
                ulonglong2 uz0 = *(const ulonglong2*)&sWih1[(64 + c0) * WPAD + k4 * 4];
                ulonglong2 uz1 = *(const ulonglong2*)&sWih1[(64 + c1) * WPAD + k4 * 4];
                ulonglong2 un0 = *(const ulonglong2*)&sWih1[(128 + c0) * WPAD + k4 * 4];
                ulonglong2 un1 = *(const ulonglong2*)&sWih1[(128 + c1) * WPAD + k4 * 4];
                ulonglong2 wr0 = *(const ulonglong2*)&sWhh1[c0 * WPAD + k4 * 4];
                ulonglong2 wr1 = *(const ulonglong2*)&sWhh1[c1 * WPAD + k4 * 4];
                ulonglong2 wz0 = *(const ulonglong2*)&sWhh1[(64 + c0) * WPAD + k4 * 4];
                ulonglong2 wz1 = *(const ulonglong2*)&sWhh1[(64 + c1) * WPAD + k4 * 4];
                ulonglong2 wn0 = *(const ulonglong2*)&sWhh1[(128 + c0) * WPAD + k4 * 4];
                ulonglong2 wn1 = *(const ulonglong2*)&sWhh1[(128 + c1) * WPAD + k4 * 4];
                #pragma unroll
                for (int i = 0; i < 4; i++) {
                    ulonglong2 gv = *(const ulonglong2*)&sH0n[(rbase + i) * HPAD + k4 * 4];
                    ulonglong2 vv = *(const ulonglong2*)&sH1c[(rbase + i) * HPAD + k4 * 4];
                    Cr[i][0]  = ffma2(gv.x, ur0.x, Cr[i][0]);
                    Cr[i][0]  = ffma2(vv.x, wr0.x, Cr[i][0]);
                    Cr[i][1]  = ffma2(gv.x, ur1.x, Cr[i][1]);
                    Cr[i][1]  = ffma2(vv.x, wr1.x, Cr[i][1]);
                    Cz[i][0]  = ffma2(gv.x, uz0.x, Cz[i][0]);
                    Cz[i][0]  = ffma2(vv.x, wz0.x, Cz[i][0]);
                    Cz[i][1]  = ffma2(gv.x, uz1.x, Cz[i][1]);
                    Cz[i][1]  = ffma2(vv.x, wz1.x, Cz[i][1]);
                    Cxn[i][0] = ffma2(gv.x, un0.x, Cxn[i][0]);
                    Cxn[i][1] = ffma2(gv.x, un1.x, Cxn[i][1]);
                    Chn[i][0] = ffma2(vv.x, wn0.x, Chn[i][0]);
                    Chn[i][1] = ffma2(vv.x, wn1.x, Chn[i][1]);
                    Cr[i][0]  = ffma2(gv.y, ur0.y, Cr[i][0]);
                    Cr[i][0]  = ffma2(vv.y, wr0.y, Cr[i][0]);
                    Cr[i][1]  = ffma2(gv.y, ur1.y, Cr[i][1]);
                    Cr[i][1]  = ffma2(vv.y, wr1.y, Cr[i][1]);
                    Cz[i][0]  = ffma2(gv.y, uz0.y, Cz[i][0]);
                    Cz[i][0]  = ffma2(vv.y, wz0.y, Cz[i][0]);
                    Cz[i][1]  = ffma2(gv.y, uz1.y, Cz[i][1]);
                    Cz[i][1]  = ffma2(vv.y, wz1.y, Cz[i][1]);
                    Cxn[i][0] = ffma2(gv.y, un0.y, Cxn[i][0]);
                    Cxn[i][1] = ffma2(gv.y, un1.y, Cxn[i][1]);
                    Chn[i][0] = ffma2(vv.y, wn0.y, Chn[i][0]);
                    Chn[i][1] = ffma2(vv.y, wn1.y, Chn[i][1]);
                }
            }

            const int cc[2] = {c0, c1};
            #pragma unroll
            for (int j = 0; j < 2; j++) {
                float sr, sz, xn, hn;
                float v0, v1, v2, v3;
                v0 = hsum2(Cr[0][j]); v1 = hsum2(Cr[1][j]);
                v2 = hsum2(Cr[2][j]); v3 = hsum2(Cr[3][j]);
                REDUCE4(v0, v1, v2, v3, sr);
                v0 = hsum2(Cz[0][j]); v1 = hsum2(Cz[1][j]);
                v2 = hsum2(Cz[2][j]); v3 = hsum2(Cz[3][j]);
                REDUCE4(v0, v1, v2, v3, sz);
                v0 = hsum2(Cxn[0][j]); v1 = hsum2(Cxn[1][j]);
                v2 = hsum2(Cxn[2][j]); v3 = hsum2(Cxn[3][j]);
                REDUCE4(v0, v1, v2, v3, xn);
                v0 = hsum2(Chn[0][j]); v1 = hsum2(Chn[1][j]);
                v2 = hsum2(Chn[2][j]); v3 = hsum2(Chn[3][j]);
                REDUCE4(v0, v1, v2, v3, hn);

                float rv = sig_fast(sr + br1[j]);
                float zv = sig_fast(sz + bz1[j]);
                float nv = tanh_fast(xn + bxn1[j] + rv * (hn + bhn1[j]));
                float ho = sH1c[myrow * HPAD + cc[j]];
                sH1n[myrow * HPAD + cc[j]] = (1.f - zv) * nv + zv * ho;
            }
        }
        __syncthreads();
    }

    // final h1 buffer = TT & 1
    const float* hf = sH1 + (TT & 1) * (GRU_ROWS * HPAD);
    for (int i = tid; i < GRU_ROWS * HH; i += GRU_THREADS) {
        int r = i >> 6, c = i & 63;
        g_h1[(size_t)r0 * HH + i] = hf[r * HPAD + c];
    }
    if (tid < GRU_ROWS) {
        float a = 0.f, b2s = 0.f;
        #pragma unroll
        for (int cc2 = 0; cc2 < HH; cc2++) {
            float h = hf[tid * HPAD + cc2];
            a   += h * Wv[cc2];
            b2s += h * Wv[HH + cc2];
        }
        g_sa[r0 + tid] = a;
        g_sb[r0 + tid] = b2s;
    }
}

// ---------------------------------------------------------------------------
// Kernel 2: streaming rel-dot v2 — shfl-free, one thread per (i,j) pair.
// 16 independent LDG.128 per pair (MLP 16); no reductions.
// ---------------------------------------------------------------------------
#define RD_THREADS 256
#define RD_BLOCKS  2048

__global__ void __launch_bounds__(RD_THREADS)
reldot_kernel(const float* __restrict__ rel, const float* __restrict__ W)
{
    __shared__ float sWv[RR];
    const int tid = threadIdx.x;
    if (tid < RR) sWv[tid] = W[2 * HH + tid];
    __syncthreads();

    #pragma unroll
    for (int pi = 0; pi < 2; pi++) {
        const int p = blockIdx.x * (RD_THREADS * 2) + pi * RD_THREADS + tid;
        const float4* rp = (const float4*)(rel + (size_t)p * RR);
        float dot = 0.f, ssum = 0.f;
        #pragma unroll
        for (int q = 0; q < 16; q++) {
            float4 v = rp[q];
            ssum += (v.x + v.y) + (v.z + v.w);
            dot  += v.x * sWv[q * 4]     + v.y * sWv[q * 4 + 1]
                  + v.z * sWv[q * 4 + 2] + v.w * sWv[q * 4 + 3];
        }
        g_dot[p] = dot;
        g_sum[p] = ssum;
    }
}

// ---------------------------------------------------------------------------
// Kernel 3: softmax + agg + FC, 8 rows per block (unchanged).
// ---------------------------------------------------------------------------
#define A3_THREADS 512

__global__ void __launch_bounds__(A3_THREADS)
att3_kernel(const float* __restrict__ bsc,
            const float* __restrict__ fc_w,
            const float* __restrict__ fc_b,
            float* __restrict__ out)
{
    __shared__ float sP[8 * NN];
    __shared__ float sT[64 * 64];
    __shared__ float sWmax[16];
    __shared__ float sWsum[16];
    __shared__ float sDen[8];
    __shared__ float sRed[16];

    const int tid  = threadIdx.x;
    const int wid  = tid >> 5;
    const int lane = tid & 31;
    const int i0   = blockIdx.x * 8;

    const int r    = wid >> 1;
    const int part = ((wid & 1) << 5) + lane;
    const int i    = i0 + r;
    const float sa_i = g_sa[i];
    const float bval = bsc[0];

    float tv[16];
    float mx = -INFINITY;
    #pragma unroll
    for (int q4 = 0; q4 < 4; q4++) {
        int j = part * 16 + q4 * 4;
        float4 d4 = *(const float4*)&g_dot[(size_t)i * NN + j];
        float4 s4 = *(const float4*)&g_sum[(size_t)i * NN + j];
        #pragma unroll
        for (int e = 0; e < 4; e++) {
            float dot  = (&d4.x)[e];
            float ssum = (&s4.x)[e];
            float w = sa_i + g_sb[j + e] + dot + bval;
            w = (w >= 0.f) ? w : SLOPE * w;
            float m  = (ssum != 0.f) ? 1.f : 0.f;
            float t  = m * w;
            if (t == 0.f) t = NEG_VAL;
            tv[q4 * 4 + e] = t;
            sP[r * NN + j + e] = m;
            mx = fmaxf(mx, t);
        }
    }
    #pragma unroll
    for (int off = 16; off; off >>= 1) mx = fmaxf(mx, __shfl_xor_sync(0xffffffffu, mx, off));
    if (lane == 0) sWmax[wid] = mx;
    __syncthreads();
    mx = fmaxf(sWmax[r * 2], sWmax[r * 2 + 1]);

    float lsum = 0.f;
    #pragma unroll
    for (int q = 0; q < 16; q++) {
        int j = part * 16 + q;
        float e = __expf(tv[q] - mx);
        lsum += e;
        sP[r * NN + j] = e * sP[r * NN + j];
    }
    #pragma unroll
    for (int off = 16; off; off >>= 1) lsum += __shfl_xor_sync(0xffffffffu, lsum, off);
    if (lane == 0) sWsum[wid] = lsum;
    __syncthreads();
    if (tid < 8) sDen[tid] = sWsum[tid * 2] + sWsum[tid * 2 + 1];
    __syncthreads();

    const int c  = tid & 63;
    const int rr = tid >> 6;
    float acc = 0.f;
    for (int tile = 0; tile < 16; tile++) {
        #pragma unroll
        for (int k = 0; k < 8; k++) {
            int e = tid + k * A3_THREADS;
            sT[e] = g_h1[(size_t)(tile * 64) * HH + e];
        }
        __syncthreads();
        const float* pr = &sP[rr * NN + tile * 64];
        #pragma unroll 16
        for (int jj = 0; jj < 64; jj++)
            acc += pr[jj] * sT[jj * 64 + c];
        __syncthreads();
    }

    const float inv = 1.0f / sDen[rr];
    float val = g_h1[(size_t)(i0 + rr) * HH + c] * fc_w[c] + acc * inv * fc_w[HH + c];
    #pragma unroll
    for (int off = 16; off; off >>= 1) val += __shfl_xor_sync(0xffffffffu, val, off);
    if (lane == 0) sRed[wid] = val;
    __syncthreads();
    if (tid < 8)
        out[i0 + tid] = sRed[tid * 2] + sRed[tid * 2 + 1] + fc_b[0];
}

// ---------------------------------------------------------------------------
// Launch: gru first on main stream, reldot forked alongside it.
// ---------------------------------------------------------------------------
extern "C" void kernel_launch(void* const* d_in, const int* in_sizes, int n_in,
                              void* d_out, int out_size)
{
    const float* x    = (const float*)d_in[0];
    const float* rel  = (const float*)d_in[1];
    const float* W    = (const float*)d_in[2];
    const float* b    = (const float*)d_in[3];
    const float* fc_w = (const float*)d_in[4];
    const float* fc_b = (const float*)d_in[5];
    const float* Wih0 = (const float*)d_in[6];
    const float* Whh0 = (const float*)d_in[7];
    const float* bih0 = (const float*)d_in[8];
    const float* bhh0 = (const float*)d_in[9];
    const float* Wih1 = (const float*)d_in[10];
    const float* Whh1 = (const float*)d_in[11];
    const float* bih1 = (const float*)d_in[12];
    const float* bhh1 = (const float*)d_in[13];
    float* out = (float*)d_out;

    const size_t gru_smem =
        (3 * GG * WPAD + GG * 8 + GRU_ROWS * 360 + 2 * 64 +
         4 * GRU_ROWS * HPAD) * sizeof(float);
    cudaFuncSetAttribute(gru_kernel, cudaFuncAttributeMaxDynamicSharedMemorySize,
                         (int)gru_smem);

    cudaStream_t s1;
    cudaEvent_t eFork, eJoin;
    cudaStreamCreateWithFlags(&s1, cudaStreamNonBlocking);
    cudaEventCreateWithFlags(&eFork, cudaEventDisableTiming);
    cudaEventCreateWithFlags(&eJoin, cudaEventDisableTiming);

    cudaEventRecord(eFork, 0);
    cudaStreamWaitEvent(s1, eFork, 0);

    gru_kernel<<<NN / GRU_ROWS, GRU_THREADS, gru_smem>>>(
        x, Wih0, Whh0, bih0, bhh0, Wih1, Whh1, bih1, bhh1, W);

    reldot_kernel<<<RD_BLOCKS, RD_THREADS, 0, s1>>>(rel, W);
    cudaEventRecord(eJoin, s1);

    cudaStreamWaitEvent(0, eJoin, 0);

    att3_kernel<<<NN / 8, A3_THREADS>>>(b, fc_w, fc_b, out);
}

// round 11
// speedup vs baseline: 2.2010x; 1.2555x over previous
#include <cuda_runtime.h>
#include <math.h>
#include <stdint.h>

// Problem constants
#define NN      1024
#define DF      6
#define TT      60
#define HH      64
#define GG      192      // 3*H
#define RR      64
#define W2      72       // weight row stride (words), kh-swizzled
#define H2      68       // h row stride (words), kh-swizzled
#define NEG_VAL (-10000.0f)
#define SLOPE   0.01f

// Inter-kernel scratch
__device__ float g_h1[NN * HH];
__device__ float g_sa[NN];
__device__ float g_sb[NN];
__device__ float g_dot[NN * NN];
__device__ float g_sum[NN * NN];

typedef unsigned long long u64;

__device__ __forceinline__ u64 ffma2(u64 a, u64 b, u64 c) {
    u64 d;
    asm("fma.rn.f32x2 %0, %1, %2, %3;" : "=l"(d) : "l"(a), "l"(b), "l"(c));
    return d;
}
__device__ __forceinline__ float hsum2(u64 v) {
    float lo, hi;
    asm("mov.b64 {%0,%1}, %2;" : "=f"(lo), "=f"(hi) : "l"(v));
    return lo + hi;
}
__device__ __forceinline__ float tanh_fast(float x) {
    float y;
    asm("tanh.approx.f32 %0, %1;" : "=f"(y) : "f"(x));
    return y;
}
__device__ __forceinline__ float sig_fast(float x) {
    return 0.5f * tanh_fast(0.5f * x) + 0.5f;
}

// Split-K pair reduction (partner = lane^1). Thread kh=0 gets full sums for
// rows rbase+{0,1}; kh=1 for rbase+{2,3}.  s0 -> row rbase+2kh, s1 -> +1.
#define RED2(v0, v1, v2, v3, s0, s1)                                          \
    {                                                                         \
        float _ta = __shfl_xor_sync(0xffffffffu, kh ? (v0) : (v2), 1);        \
        float _tb = __shfl_xor_sync(0xffffffffu, kh ? (v1) : (v3), 1);        \
        (s0) = (kh ? (v2) : (v0)) + _ta;                                      \
        (s1) = (kh ? (v3) : (v1)) + _tb;                                      \
    }

// ---------------------------------------------------------------------------
// Kernel 1: fused 2-layer GRU v5 — merged GEMM phase (L1(t-1) + L0(t)),
// one __syncthreads per step. 128 blocks x 8 rows, 256 threads.
// ---------------------------------------------------------------------------
#define GRU_THREADS 256
#define GRU_ROWS    8

__global__ void __launch_bounds__(GRU_THREADS, 1)
gru_kernel(const float* __restrict__ x,
           const float* __restrict__ Wih0, const float* __restrict__ Whh0,
           const float* __restrict__ bih0, const float* __restrict__ bhh0,
           const float* __restrict__ Wih1, const float* __restrict__ Whh1,
           const float* __restrict__ bih1, const float* __restrict__ bhh1,
           const float* __restrict__ Wv)
{
    extern __shared__ float smem[];
    float* sWhh0 = smem;                          // 192*72
    float* sWih1 = sWhh0 + GG * W2;               // 192*72
    float* sWhh1 = sWih1 + GG * W2;               // 192*72
    float* sWih0 = sWhh1 + GG * W2;               // 192*8
    float* sX    = sWih0 + GG * 8;                // 8*360
    float* sXt   = sX + GRU_ROWS * 360;           // 2*64
    float* sH0   = sXt + 2 * 64;                  // 2*8*68
    float* sH1   = sH0 + 2 * GRU_ROWS * H2;       // 2*8*68

    const int tid = threadIdx.x;
    const int r0  = blockIdx.x * GRU_ROWS;

    // ---- init: swizzled weight load, x, zero h ----
    for (int i = tid; i < GG * HH; i += GRU_THREADS) {
        int o = i >> 6, k = i & 63;
        int w = o * W2 + k + ((k >= 32) ? 4 : 0);
        sWhh0[w] = Whh0[i];
        sWih1[w] = Wih1[i];
        sWhh1[w] = Whh1[i];
    }
    for (int i = tid; i < GG * DF; i += GRU_THREADS) {
        int o = i / DF, d = i % DF;
        sWih0[o * 8 + d] = Wih0[i];
    }
    for (int i = tid; i < GRU_ROWS * 360; i += GRU_THREADS) {
        int r = i / 360, cc = i % 360;
        sX[i] = x[(size_t)(r0 + r) * 360 + cc];
    }
    for (int i = tid; i < 2 * GRU_ROWS * H2; i += GRU_THREADS) {
        sH0[i] = 0.f; sH1[i] = 0.f;
    }
    if (tid < GRU_ROWS * DF) {
        int r = tid / DF, d = tid % DF;
        sXt[r * 8 + d] = sX[r * 360 + d * TT + 0];
    }

    // ---- thread mapping ----
    const int lane  = tid & 31;
    const int warp  = tid >> 5;
    const int kh    = lane & 1;              // K half
    const int rg    = (lane >> 1) & 1;       // 4-row group
    const int cl    = lane >> 2;             // 0..7
    const int c     = warp * 8 + cl;         // 0..63
    const int rbase = rg * 4;
    const int R0    = rbase + 2 * kh;        // owned rows R0, R0+1
    const int wob   = 36 * kh;               // swizzled word offset of K-half
    const int swc   = (c >= 32) ? 4 : 0;

    const float br0  = bih0[c] + bhh0[c];
    const float bz0  = bih0[64 + c] + bhh0[64 + c];
    const float bxn0 = bih0[128 + c];
    const float bhn0 = bhh0[128 + c];
    const float br1  = bih1[c] + bhh1[c];
    const float bz1  = bih1[64 + c] + bhh1[64 + c];
    const float bxn1 = bih1[128 + c];
    const float bhn1 = bhh1[128 + c];
    __syncthreads();

    // ---- it = 0: h0[1] = gates(x0, h=0); h1[0] stays 0 ----
    {
        #pragma unroll
        for (int rr = 0; rr < 2; rr++) {
            int R = R0 + rr;
            float xr = 0.f, xz = 0.f, xn = 0.f;
            #pragma unroll
            for (int d = 0; d < DF; d++) {
                float xv = sXt[R * 8 + d];
                xr += xv * sWih0[c * 8 + d];
                xz += xv * sWih0[(64 + c) * 8 + d];
                xn += xv * sWih0[(128 + c) * 8 + d];
            }
            float rv = sig_fast(xr + br0);
            float zv = sig_fast(xz + bz0);
            float nv = tanh_fast(xn + bxn0 + rv * bhn0);
            sH0[1 * (GRU_ROWS * H2) + R * H2 + c + swc] = (1.f - zv) * nv;
        }
        if (tid < GRU_ROWS * DF) {
            int r = tid / DF, d = tid % DF;
            sXt[64 + r * 8 + d] = sX[r * 360 + d * TT + 1];
        }
    }
    __syncthreads();

    // ---- main loop: it = 1..TT-1 ----
    for (int it = 1; it < TT; ++it) {
        const int pc = it & 1, pn = pc ^ 1;
        float* H0c = sH0 + pc * (GRU_ROWS * H2);
        float* H0n = sH0 + pn * (GRU_ROWS * H2);
        float* H1c = sH1 + pc * (GRU_ROWS * H2);
        float* H1n = sH1 + pn * (GRU_ROWS * H2);

        u64 Ar[4], Az[4], An[4], Br[4], Bz[4], Bxn[4], Bhn[4];
        #pragma unroll
        for (int i = 0; i < 4; i++) {
            Ar[i] = 0; Az[i] = 0; An[i] = 0;
            Br[i] = 0; Bz[i] = 0; Bxn[i] = 0; Bhn[i] = 0;
        }

        #pragma unroll
        for (int q = 0; q < 8; q++) {
            const int wo = wob + q * 4;
            ulonglong2 ar = *(const ulonglong2*)&sWhh0[c * W2 + wo];
            ulonglong2 az = *(const ulonglong2*)&sWhh0[(64 + c) * W2 + wo];
            ulonglong2 an = *(const ulonglong2*)&sWhh0[(128 + c) * W2 + wo];
            ulonglong2 ur = *(const ulonglong2*)&sWih1[c * W2 + wo];
            ulonglong2 uz = *(const ulonglong2*)&sWih1[(64 + c) * W2 + wo];
            ulonglong2 un = *(const ulonglong2*)&sWih1[(128 + c) * W2 + wo];
            ulonglong2 vr = *(const ulonglong2*)&sWhh1[c * W2 + wo];
            ulonglong2 vz = *(const ulonglong2*)&sWhh1[(64 + c) * W2 + wo];
            ulonglong2 vn = *(const ulonglong2*)&sWhh1[(128 + c) * W2 + wo];
            #pragma unroll
            for (int i = 0; i < 4; i++) {
                ulonglong2 h0v = *(const ulonglong2*)&H0c[(rbase + i) * H2 + wo];
                ulonglong2 h1v = *(const ulonglong2*)&H1c[(rbase + i) * H2 + wo];
                Ar[i]  = ffma2(h0v.x, ar.x, Ar[i]);
                Az[i]  = ffma2(h0v.x, az.x, Az[i]);
                An[i]  = ffma2(h0v.x, an.x, An[i]);
                Br[i]  = ffma2(h0v.x, ur.x, Br[i]);
                Bz[i]  = ffma2(h0v.x, uz.x, Bz[i]);
                Bxn[i] = ffma2(h0v.x, un.x, Bxn[i]);
                Br[i]  = ffma2(h1v.x, vr.x, Br[i]);
                Bz[i]  = ffma2(h1v.x, vz.x, Bz[i]);
                Bhn[i] = ffma2(h1v.x, vn.x, Bhn[i]);
                Ar[i]  = ffma2(h0v.y, ar.y, Ar[i]);
                Az[i]  = ffma2(h0v.y, az.y, Az[i]);
                An[i]  = ffma2(h0v.y, an.y, An[i]);
                Br[i]  = ffma2(h0v.y, ur.y, Br[i]);
                Bz[i]  = ffma2(h0v.y, uz.y, Bz[i]);
                Bxn[i] = ffma2(h0v.y, un.y, Bxn[i]);
                Br[i]  = ffma2(h1v.y, vr.y, Br[i]);
                Bz[i]  = ffma2(h1v.y, vz.y, Bz[i]);
                Bhn[i] = ffma2(h1v.y, vn.y, Bhn[i]);
            }
        }

        float sAr[2], sAz[2], sAn[2], sBr[2], sBz[2], sBxn[2], sBhn[2];
        {
            float v0, v1, v2, v3;
            v0 = hsum2(Ar[0]);  v1 = hsum2(Ar[1]);  v2 = hsum2(Ar[2]);  v3 = hsum2(Ar[3]);
            RED2(v0, v1, v2, v3, sAr[0], sAr[1]);
            v0 = hsum2(Az[0]);  v1 = hsum2(Az[1]);  v2 = hsum2(Az[2]);  v3 = hsum2(Az[3]);
            RED2(v0, v1, v2, v3, sAz[0], sAz[1]);
            v0 = hsum2(An[0]);  v1 = hsum2(An[1]);  v2 = hsum2(An[2]);  v3 = hsum2(An[3]);
            RED2(v0, v1, v2, v3, sAn[0], sAn[1]);
            v0 = hsum2(Br[0]);  v1 = hsum2(Br[1]);  v2 = hsum2(Br[2]);  v3 = hsum2(Br[3]);
            RED2(v0, v1, v2, v3, sBr[0], sBr[1]);
            v0 = hsum2(Bz[0]);  v1 = hsum2(Bz[1]);  v2 = hsum2(Bz[2]);  v3 = hsum2(Bz[3]);
            RED2(v0, v1, v2, v3, sBz[0], sBz[1]);
            v0 = hsum2(Bxn[0]); v1 = hsum2(Bxn[1]); v2 = hsum2(Bxn[2]); v3 = hsum2(Bxn[3]);
            RED2(v0, v1, v2, v3, sBxn[0], sBxn[1]);
            v0 = hsum2(Bhn[0]); v1 = hsum2(Bhn[1]); v2 = hsum2(Bhn[2]); v3 = hsum2(Bhn[3]);
            RED2(v0, v1, v2, v3, sBhn[0], sBhn[1]);
        }

        // ---- gates (no barrier needed: opposite parity buffers) ----
        #pragma unroll
        for (int rr = 0; rr < 2; rr++) {
            int R = R0 + rr;
            // L0: h0[it+1]
            float xr = 0.f, xz = 0.f, xn = 0.f;
            #pragma unroll
            for (int d = 0; d < DF; d++) {
                float xv = sXt[pc * 64 + R * 8 + d];
                xr += xv * sWih0[c * 8 + d];
                xz += xv * sWih0[(64 + c) * 8 + d];
                xn += xv * sWih0[(128 + c) * 8 + d];
            }
            float rv = sig_fast(xr + sAr[rr] + br0);
            float zv = sig_fast(xz + sAz[rr] + bz0);
            float nv = tanh_fast(xn + bxn0 + rv * (sAn[rr] + bhn0));
            float h0old = H0c[R * H2 + c + swc];
            H0n[R * H2 + c + swc] = (1.f - zv) * nv + zv * h0old;
            // L1: h1[it]
            float rv1 = sig_fast(sBr[rr] + br1);
            float zv1 = sig_fast(sBz[rr] + bz1);
            float nv1 = tanh_fast(sBxn[rr] + bxn1 + rv1 * (sBhn[rr] + bhn1));
            float h1old = H1c[R * H2 + c + swc];
            H1n[R * H2 + c + swc] = (1.f - zv1) * nv1 + zv1 * h1old;
        }
        if (it + 1 < TT && tid < GRU_ROWS * DF) {
            int r = tid / DF, d = tid % DF;
            sXt[pn * 64 + r * 8 + d] = sX[r * 360 + d * TT + (it + 1)];
        }
        __syncthreads();
    }

    // ---- epilogue: B(TT-1) gemm + L1 gates -> h1[TT] ----
    {
        float* H0c = sH0 + ((TT) & 1) * (GRU_ROWS * H2);   // h0[60]
        float* H1c = sH1 + ((TT) & 1) * (GRU_ROWS * H2);   // h1[59]
        float* H1f = sH1 + (((TT) & 1) ^ 1) * (GRU_ROWS * H2);

        u64 Br[4], Bz[4], Bxn[4], Bhn[4];
        #pragma unroll
        for (int i = 0; i < 4; i++) { Br[i] = 0; Bz[i] = 0; Bxn[i] = 0; Bhn[i] = 0; }

        #pragma unroll
        for (int q = 0; q < 8; q++) {
            const int wo = wob + q * 4;
            ulonglong2 ur = *(const ulonglong2*)&sWih1[c * W2 + wo];
            ulonglong2 uz = *(const ulonglong2*)&sWih1[(64 + c) * W2 + wo];
            ulonglong2 un = *(const ulonglong2*)&sWih1[(128 + c) * W2 + wo];
            ulonglong2 vr = *(const ulonglong2*)&sWhh1[c * W2 + wo];
            ulonglong2 vz = *(const ulonglong2*)&sWhh1[(64 + c) * W2 + wo];
            ulonglong2 vn = *(const ulonglong2*)&sWhh1[(128 + c) * W2 + wo];
            #pragma unroll
            for (int i = 0; i < 4; i++) {
                ulonglong2 h0v = *(const ulonglong2*)&H0c[(rbase + i) * H2 + wo];
                ulonglong2 h1v = *(const ulonglong2*)&H1c[(rbase + i) * H2 + wo];
                Br[i]  = ffma2(h0v.x, ur.x, Br[i]);
                Bz[i]  = ffma2(h0v.x, uz.x, Bz[i]);
                Bxn[i] = ffma2(h0v.x, un.x, Bxn[i]);
                Br[i]  = ffma2(h1v.x, vr.x, Br[i]);
                Bz[i]  = ffma2(h1v.x, vz.x, Bz[i]);
                Bhn[i] = ffma2(h1v.x, vn.x, Bhn[i]);
                Br[i]  = ffma2(h0v.y, ur.y, Br[i]);
                Bz[i]  = ffma2(h0v.y, uz.y, Bz[i]);
                Bxn[i] = ffma2(h0v.y, un.y, Bxn[i]);
                Br[i]  = ffma2(h1v.y, vr.y, Br[i]);
                Bz[i]  = ffma2(h1v.y, vz.y, Bz[i]);
                Bhn[i] = ffma2(h1v.y, vn.y, Bhn[i]);
            }
        }
        float sBr[2], sBz[2], sBxn[2], sBhn[2];
        {
            float v0, v1, v2, v3;
            v0 = hsum2(Br[0]);  v1 = hsum2(Br[1]);  v2 = hsum2(Br[2]);  v3 = hsum2(Br[3]);
            RED2(v0, v1, v2, v3, sBr[0], sBr[1]);
            v0 = hsum2(Bz[0]);  v1 = hsum2(Bz[1]);  v2 = hsum2(Bz[2]);  v3 = hsum2(Bz[3]);
            RED2(v0, v1, v2, v3, sBz[0], sBz[1]);
            v0 = hsum2(Bxn[0]); v1 = hsum2(Bxn[1]); v2 = hsum2(Bxn[2]); v3 = hsum2(Bxn[3]);
            RED2(v0, v1, v2, v3, sBxn[0], sBxn[1]);
            v0 = hsum2(Bhn[0]); v1 = hsum2(Bhn[1]); v2 = hsum2(Bhn[2]); v3 = hsum2(Bhn[3]);
            RED2(v0, v1, v2, v3, sBhn[0], sBhn[1]);
        }
        #pragma unroll
        for (int rr = 0; rr < 2; rr++) {
            int R = R0 + rr;
            float rv1 = sig_fast(sBr[rr] + br1);
            float zv1 = sig_fast(sBz[rr] + bz1);
            float nv1 = tanh_fast(sBxn[rr] + bxn1 + rv1 * (sBhn[rr] + bhn1));
            float h1old = H1c[R * H2 + c + swc];
            H1f[R * H2 + c + swc] = (1.f - zv1) * nv1 + zv1 * h1old;
        }
    }
    __syncthreads();

    // ---- outputs (unswizzle) ----
    const float* hf = sH1 + (((TT) & 1) ^ 1) * (GRU_ROWS * H2);
    for (int i = tid; i < GRU_ROWS * HH; i += GRU_THREADS) {
        int r = i >> 6, cc = i & 63;
        g_h1[(size_t)r0 * HH + i] = hf[r * H2 + cc + ((cc >= 32) ? 4 : 0)];
    }
    if (tid < GRU_ROWS) {
        float a = 0.f, b2s = 0.f;
        #pragma unroll
        for (int cc = 0; cc < HH; cc++) {
            float h = hf[tid * H2 + cc + ((cc >= 32) ? 4 : 0)];
            a   += h * Wv[cc];
            b2s += h * Wv[HH + cc];
        }
        g_sa[r0 + tid] = a;
        g_sb[r0 + tid] = b2s;
    }
}

// ---------------------------------------------------------------------------
// Kernel 2: streaming rel-dot (R6 proven version: 16-lane coalesced + shfl).
// ---------------------------------------------------------------------------
#define RD_THREADS 256
#define RD_BLOCKS  2048

__global__ void __launch_bounds__(RD_THREADS)
reldot_kernel(const float* __restrict__ rel, const float* __restrict__ W)
{
    __shared__ float sWv[RR];
    const int tid = threadIdx.x;
    if (tid < RR) sWv[tid] = W[2 * HH + tid];
    __syncthreads();

    const int lane16 = tid & 15;
    const int grp    = tid >> 4;
    const float4 wv  = *(const float4*)&sWv[lane16 * 4];
    const int stride = RD_BLOCKS * 16;

    for (int p = blockIdx.x * 16 + grp; p < NN * NN; p += stride) {
        float4 v = *(const float4*)&rel[(size_t)p * RR + lane16 * 4];
        float dot  = v.x * wv.x + v.y * wv.y + v.z * wv.z + v.w * wv.w;
        float ssum = v.x + v.y + v.z + v.w;
        #pragma unroll
        for (int off = 8; off; off >>= 1) {
            dot  += __shfl_xor_sync(0xffffffffu, dot,  off);
            ssum += __shfl_xor_sync(0xffffffffu, ssum, off);
        }
        if (lane16 == 0) {
            g_dot[p] = dot;
            g_sum[p] = ssum;
        }
    }
}

// ---------------------------------------------------------------------------
// Kernel 3: softmax + agg + FC, 8 rows per block (unchanged).
// ---------------------------------------------------------------------------
#define A3_THREADS 512

__global__ void __launch_bounds__(A3_THREADS)
att3_kernel(const float* __restrict__ bsc,
            const float* __restrict__ fc_w,
            const float* __restrict__ fc_b,
            float* __restrict__ out)
{
    __shared__ float sP[8 * NN];
    __shared__ float sT[64 * 64];
    __shared__ float sWmax[16];
    __shared__ float sWsum[16];
    __shared__ float sDen[8];
    __shared__ float sRed[16];

    const int tid  = threadIdx.x;
    const int wid  = tid >> 5;
    const int lane = tid & 31;
    const int i0   = blockIdx.x * 8;

    const int r    = wid >> 1;
    const int part = ((wid & 1) << 5) + lane;
    const int i    = i0 + r;
    const float sa_i = g_sa[i];
    const float bval = bsc[0];

    float tv[16];
    float mx = -INFINITY;
    #pragma unroll
    for (int q4 = 0; q4 < 4; q4++) {
        int j = part * 16 + q4 * 4;
        float4 d4 = *(const float4*)&g_dot[(size_t)i * NN + j];
        float4 s4 = *(const float4*)&g_sum[(size_t)i * NN + j];
        #pragma unroll
        for (int e = 0; e < 4; e++) {
            float dot  = (&d4.x)[e];
            float ssum = (&s4.x)[e];
            float w = sa_i + g_sb[j + e] + dot + bval;
            w = (w >= 0.f) ? w : SLOPE * w;
            float m  = (ssum != 0.f) ? 1.f : 0.f;
            float t  = m * w;
            if (t == 0.f) t = NEG_VAL;
            tv[q4 * 4 + e] = t;
            sP[r * NN + j + e] = m;
            mx = fmaxf(mx, t);
        }
    }
    #pragma unroll
    for (int off = 16; off; off >>= 1) mx = fmaxf(mx, __shfl_xor_sync(0xffffffffu, mx, off));
    if (lane == 0) sWmax[wid] = mx;
    __syncthreads();
    mx = fmaxf(sWmax[r * 2], sWmax[r * 2 + 1]);

    float lsum = 0.f;
    #pragma unroll
    for (int q = 0; q < 16; q++) {
        int j = part * 16 + q;
        float e = __expf(tv[q] - mx);
        lsum += e;
        sP[r * NN + j] = e * sP[r * NN + j];
    }
    #pragma unroll
    for (int off = 16; off; off >>= 1) lsum += __shfl_xor_sync(0xffffffffu, lsum, off);
    if (lane == 0) sWsum[wid] = lsum;
    __syncthreads();
    if (tid < 8) sDen[tid] = sWsum[tid * 2] + sWsum[tid * 2 + 1];
    __syncthreads();

    const int c  = tid & 63;
    const int rr = tid >> 6;
    float acc = 0.f;
    for (int tile = 0; tile < 16; tile++) {
        #pragma unroll
        for (int k = 0; k < 8; k++) {
            int e = tid + k * A3_THREADS;
            sT[e] = g_h1[(size_t)(tile * 64) * HH + e];
        }
        __syncthreads();
        const float* pr = &sP[rr * NN + tile * 64];
        #pragma unroll 16
        for (int jj = 0; jj < 64; jj++)
            acc += pr[jj] * sT[jj * 64 + c];
        __syncthreads();
    }

    const float inv = 1.0f / sDen[rr];
    float val = g_h1[(size_t)(i0 + rr) * HH + c] * fc_w[c] + acc * inv * fc_w[HH + c];
    #pragma unroll
    for (int off = 16; off; off >>= 1) val += __shfl_xor_sync(0xffffffffu, val, off);
    if (lane == 0) sRed[wid] = val;
    __syncthreads();
    if (tid < 8)
        out[i0 + tid] = sRed[tid * 2] + sRed[tid * 2 + 1] + fc_b[0];
}

// ---------------------------------------------------------------------------
// Launch: gru first on main stream, reldot forked alongside it.
// ---------------------------------------------------------------------------
extern "C" void kernel_launch(void* const* d_in, const int* in_sizes, int n_in,
                              void* d_out, int out_size)
{
    const float* x    = (const float*)d_in[0];
    const float* rel  = (const float*)d_in[1];
    const float* W    = (const float*)d_in[2];
    const float* b    = (const float*)d_in[3];
    const float* fc_w = (const float*)d_in[4];
    const float* fc_b = (const float*)d_in[5];
    const float* Wih0 = (const float*)d_in[6];
    const float* Whh0 = (const float*)d_in[7];
    const float* bih0 = (const float*)d_in[8];
    const float* bhh0 = (const float*)d_in[9];
    const float* Wih1 = (const float*)d_in[10];
    const float* Whh1 = (const float*)d_in[11];
    const float* bih1 = (const float*)d_in[12];
    const float* bhh1 = (const float*)d_in[13];
    float* out = (float*)d_out;

    const size_t gru_smem =
        (3 * GG * W2 + GG * 8 + GRU_ROWS * 360 + 2 * 64 +
         4 * GRU_ROWS * H2) * sizeof(float);
    cudaFuncSetAttribute(gru_kernel, cudaFuncAttributeMaxDynamicSharedMemorySize,
                         (int)gru_smem);

    cudaStream_t s1;
    cudaEvent_t eFork, eJoin;
    cudaStreamCreateWithFlags(&s1, cudaStreamNonBlocking);
    cudaEventCreateWithFlags(&eFork, cudaEventDisableTiming);
    cudaEventCreateWithFlags(&eJoin, cudaEventDisableTiming);

    cudaEventRecord(eFork, 0);
    cudaStreamWaitEvent(s1, eFork, 0);

    gru_kernel<<<NN / GRU_ROWS, GRU_THREADS, gru_smem>>>(
        x, Wih0, Whh0, bih0, bhh0, Wih1, Whh1, bih1, bhh1, W);

    reldot_kernel<<<RD_BLOCKS, RD_THREADS, 0, s1>>>(rel, W);
    cudaEventRecord(eJoin, s1);

    cudaStreamWaitEvent(0, eJoin, 0);

    att3_kernel<<<NN / 8, A3_THREADS>>>(b, fc_w, fc_b, out);
}